// round 1
// baseline (speedup 1.0000x reference)
#include <cuda_runtime.h>
#include <float.h>
#include <math.h>

// Problem constants (fixed by setup_inputs)
#define BB 2
#define CC 256
#define NN 64
#define NCLS 10
#define IMG 512

// Scratch: templates per level/batch, stored [level][b][c][n] so that for a
// fixed channel c the 64 per-user values are contiguous (float4 LDS in cor).
__device__ float g_tmpl[3 * BB * CC * NN];

// Detect whether idx/labels arrived as int64 (stride 2 in int32 words) or
// int32 (stride 1). labels values are in [1,10]; for int64 little-endian the
// odd int32 words are always 0, for int32 they are labels[1],[3],[5] != 0.
__device__ __forceinline__ int lab_stride(const int* __restrict__ lab) {
    return ((lab[1] | lab[3] | lab[5]) == 0) ? 2 : 1;
}

// ---------------------------------------------------------------------------
// Kernel 1: templates. One block per (level, b, n); thread = channel.
// tmpl[b,n,c] = (sum over 7x7 window of w(y,x) * feat[b,c,y,x]) / (Sx*Sy+1e-8)
// and 0 when idx[b,n] == -1.
// ---------------------------------------------------------------------------
__global__ void tmpl_kernel(const float* __restrict__ x0,
                            const float* __restrict__ x1,
                            const float* __restrict__ x2,
                            const float* __restrict__ centers,
                            const int* __restrict__ idxp,
                            const int* __restrict__ labp)
{
    __shared__ float swx[7], swy[7];
    __shared__ float sinv;
    __shared__ int sbnd[4]; // xlo, nx, ylo, ny

    const int bid   = blockIdx.x;          // [0, 3*B*N)
    const int level = bid / (BB * NN);
    const int r     = bid % (BB * NN);
    const int b     = r / NN;
    const int n     = r % NN;

    const int W = 64 >> level;             // H == W per level
    const int s = 8 << level;              // image stride

    if (threadIdx.x == 0) {
        const float cx = centers[(b * NN + n) * 2 + 0];
        const float cy = centers[(b * NN + n) * 2 + 1];
        const int istr = lab_stride(labp);
        const int idxv = idxp[(b * NN + n) * istr];

        // nearest grid cell (cell u sits at image coord u*s + 0.5)
        int ux = (int)floorf((cx - 0.5f) / (float)s + 0.5f);
        int uy = (int)floorf((cy - 0.5f) / (float)s + 0.5f);
        int xlo = max(0, ux - 3), xhi = min(W - 1, ux + 3);
        int ylo = max(0, uy - 3), yhi = min(W - 1, uy + 3);
        int nx = xhi - xlo + 1, ny = yhi - ylo + 1;

        const float alpha = -1.0f / 18.0f;  // -0.5/sigma^2, sigma=3
        float Sx = 0.f, Sy = 0.f;
        for (int i = 0; i < nx; i++) {
            float d = (float)((xlo + i) * s) + 0.5f - cx;
            float w = expf(alpha * d * d);
            swx[i] = w; Sx += w;
        }
        for (int j = 0; j < ny; j++) {
            float d = (float)((ylo + j) * s) + 0.5f - cy;
            float w = expf(alpha * d * d);
            swy[j] = w; Sy += w;
        }
        sinv = (idxv == -1) ? 0.0f : 1.0f / (Sx * Sy + 1e-8f);
        sbnd[0] = xlo; sbnd[1] = nx; sbnd[2] = ylo; sbnd[3] = ny;
    }
    __syncthreads();

    const float* feat = (level == 0) ? x0 : (level == 1) ? x1 : x2;
    const int xlo = sbnd[0], nx = sbnd[1], ylo = sbnd[2], ny = sbnd[3];
    const int c = threadIdx.x;
    const float* fb = feat + ((size_t)(b * CC + c)) * W * W;

    float acc = 0.f;
    for (int j = 0; j < ny; j++) {
        const float* rowp = fb + (ylo + j) * W + xlo;
        float rs = 0.f;
        #pragma unroll 7
        for (int i = 0; i < nx; i++) rs += swx[i] * __ldg(rowp + i);
        acc += swy[j] * rs;
    }
    g_tmpl[((size_t)(level * BB + b) * CC + c) * NN + n] = acc * sinv;
}

// ---------------------------------------------------------------------------
// Kernel 2: correlation + class-max + concat output, fused.
// Block = (level, b, 64-pixel tile), 128 threads.
// Each warp: lanes 0-15 / 16-31 handle the same 16 pixels for channel halves
// [0,128) / [128,256); acc[64] per thread; shfl-xor-16 combines halves.
// Feat passthrough (out channels 0..255) written from the same loads.
// ---------------------------------------------------------------------------
__global__ void cor_kernel(const float* __restrict__ x0,
                           const float* __restrict__ x1,
                           const float* __restrict__ x2,
                           const int* __restrict__ labp,
                           float* __restrict__ out)
{
    extern __shared__ float sT[];          // [256][64] templates, c-major
    __shared__ int slab[NN];

    const int bid = blockIdx.x;
    int level, b, tile;
    if (bid < 128)       { level = 0; b = bid >> 6;          tile = bid & 63; }
    else if (bid < 160)  { level = 1; int q = bid - 128; b = q >> 4; tile = q & 15; }
    else                 { level = 2; int q = bid - 160; b = q >> 2; tile = q & 3;  }

    const int W  = 64 >> level;
    const int HW = W * W;
    const float* feat = (level == 0) ? x0 : (level == 1) ? x1 : x2;
    const size_t outOff = (level == 0) ? 0
                        : (level == 1) ? (size_t)BB * 266 * 4096
                        : (size_t)BB * 266 * (4096 + 1024);

    // stage templates + labels into shared
    {
        const float4* src = (const float4*)(g_tmpl + (size_t)(level * BB + b) * CC * NN);
        float4* dst = (float4*)sT;
        for (int i = threadIdx.x; i < CC * NN / 4; i += blockDim.x) dst[i] = src[i];
        if (threadIdx.x < NN) {
            int lstr = lab_stride(labp);
            slab[threadIdx.x] = labp[(b * NN + threadIdx.x) * lstr];
        }
    }
    __syncthreads();

    const int lane  = threadIdx.x & 31;
    const int warp  = threadIdx.x >> 5;
    const int chalf = lane >> 4;
    const int p     = tile * 64 + warp * 16 + (lane & 15);
    const int cbase = chalf * 128;

    const float* fptr = feat + ((size_t)(b * CC + cbase)) * HW + p;
    float* optr = out + outOff + ((size_t)(b * 266 + cbase)) * HW + p;

    float acc[NN];
    #pragma unroll
    for (int n = 0; n < NN; n++) acc[n] = 0.f;

    #pragma unroll 2
    for (int c = 0; c < 128; c++) {
        const float f = fptr[(size_t)c * HW];
        optr[(size_t)c * HW] = f;                       // feat passthrough
        const float4* t4 = (const float4*)&sT[(cbase + c) * NN];
        #pragma unroll
        for (int q = 0; q < 16; q++) {
            float4 t = t4[q];                           // broadcast LDS.128
            acc[4 * q + 0] += t.x * f;
            acc[4 * q + 1] += t.y * f;
            acc[4 * q + 2] += t.z * f;
            acc[4 * q + 3] += t.w * f;
        }
    }

    // combine channel halves
    #pragma unroll
    for (int n = 0; n < NN; n++)
        acc[n] += __shfl_xor_sync(0xffffffffu, acc[n], 16);

    if (chalf == 0) {
        float* oc = out + outOff + ((size_t)(b * 266 + 256)) * HW + p;
        #pragma unroll
        for (int k = 0; k < NCLS; k++) {
            float m = -FLT_MAX;
            int any = 0;
            #pragma unroll
            for (int n = 0; n < NN; n++) {
                if (slab[n] == k + 1) { any = 1; m = fmaxf(m, acc[n]); }
            }
            oc[(size_t)k * HW] = any ? m : 0.f;
        }
    }
}

// ---------------------------------------------------------------------------
extern "C" void kernel_launch(void* const* d_in, const int* in_sizes, int n_in,
                              void* d_out, int out_size)
{
    const float* x0      = (const float*)d_in[0];
    const float* x1      = (const float*)d_in[1];
    const float* x2      = (const float*)d_in[2];
    const float* centers = (const float*)d_in[3];
    const int*   idxp    = (const int*)d_in[4];
    const int*   labp    = (const int*)d_in[5];
    float* out = (float*)d_out;

    cudaFuncSetAttribute(cor_kernel, cudaFuncAttributeMaxDynamicSharedMemorySize,
                         CC * NN * (int)sizeof(float));

    tmpl_kernel<<<3 * BB * NN, CC>>>(x0, x1, x2, centers, idxp, labp);
    cor_kernel<<<168, 128, CC * NN * (int)sizeof(float)>>>(x0, x1, x2, labp, out);
}

// round 4
// speedup vs baseline: 1.1954x; 1.1954x over previous
#include <cuda_runtime.h>
#include <float.h>
#include <math.h>
#include <stdint.h>

#define BB 2
#define CC 256
#define NN 64
#define NCLS 10

// padded per-cgroup template region: 64ch*64u + 4 pad words (16B-aligned;
// 4100 mod 32 = 4 -> cgroups start on banks {0,4,8,12}: conflict-free)
#define CGPAD 4100

// Scratch: templates [level][b][c][n] (n contiguous for vector LDS in cor).
__device__ float g_tmpl[3 * BB * CC * NN];

// idx/labels may arrive as int64 (stride 2 int32 words, odd words 0) or int32.
__device__ __forceinline__ int lab_stride(const int* __restrict__ lab) {
    return ((lab[1] | lab[3] | lab[5]) == 0) ? 2 : 1;
}

// ---------------------------------------------------------------------------
// Kernel 1: templates (EXACT copy of the R1 kernel that passed).
// One block per (level, b, n); thread = channel.
// ---------------------------------------------------------------------------
__global__ void tmpl_kernel(const float* __restrict__ x0,
                            const float* __restrict__ x1,
                            const float* __restrict__ x2,
                            const float* __restrict__ centers,
                            const int* __restrict__ idxp,
                            const int* __restrict__ labp)
{
    __shared__ float swx[7], swy[7];
    __shared__ float sinv;
    __shared__ int sbnd[4]; // xlo, nx, ylo, ny

    const int bid   = blockIdx.x;          // [0, 3*B*N)
    const int level = bid / (BB * NN);
    const int r     = bid % (BB * NN);
    const int b     = r / NN;
    const int n     = r % NN;

    const int W = 64 >> level;             // H == W per level
    const int s = 8 << level;              // image stride

    if (threadIdx.x == 0) {
        const float cx = centers[(b * NN + n) * 2 + 0];
        const float cy = centers[(b * NN + n) * 2 + 1];
        const int istr = lab_stride(labp);
        const int idxv = idxp[(b * NN + n) * istr];

        int ux = (int)floorf((cx - 0.5f) / (float)s + 0.5f);
        int uy = (int)floorf((cy - 0.5f) / (float)s + 0.5f);
        int xlo = max(0, ux - 3), xhi = min(W - 1, ux + 3);
        int ylo = max(0, uy - 3), yhi = min(W - 1, uy + 3);
        int nx = xhi - xlo + 1, ny = yhi - ylo + 1;

        const float alpha = -1.0f / 18.0f;  // -0.5/sigma^2, sigma=3
        float Sx = 0.f, Sy = 0.f;
        for (int i = 0; i < nx; i++) {
            float d = (float)((xlo + i) * s) + 0.5f - cx;
            float w = expf(alpha * d * d);
            swx[i] = w; Sx += w;
        }
        for (int j = 0; j < ny; j++) {
            float d = (float)((ylo + j) * s) + 0.5f - cy;
            float w = expf(alpha * d * d);
            swy[j] = w; Sy += w;
        }
        sinv = (idxv == -1) ? 0.0f : 1.0f / (Sx * Sy + 1e-8f);
        sbnd[0] = xlo; sbnd[1] = nx; sbnd[2] = ylo; sbnd[3] = ny;
    }
    __syncthreads();

    const float* feat = (level == 0) ? x0 : (level == 1) ? x1 : x2;
    const int xlo = sbnd[0], nx = sbnd[1], ylo = sbnd[2], ny = sbnd[3];
    const int c = threadIdx.x;
    const float* fb = feat + ((size_t)(b * CC + c)) * W * W;

    float acc = 0.f;
    for (int j = 0; j < ny; j++) {
        const float* rowp = fb + (ylo + j) * W + xlo;
        float rs = 0.f;
        #pragma unroll 7
        for (int i = 0; i < nx; i++) rs += swx[i] * __ldg(rowp + i);
        acc += swy[j] * rs;
    }
    g_tmpl[((size_t)(level * BB + b) * CC + c) * NN + n] = acc * sinv;
}

// ---------------------------------------------------------------------------
// Kernel 2: correlation + class-max + concat, fused. 336 blocks, 256 threads.
// Block = (level, b, 32-pixel tile). Warp lanes: px8 = lane&7 (pixel),
// cg = lane>>3 (4 x 64-channel groups). Warp pairs split the 64 users
// (up = warp&1, acc = 16 x f32x2). fma.rn.f32x2 halves FFMA count.
// ---------------------------------------------------------------------------
__global__ void __launch_bounds__(256) cor_kernel(
    const float* __restrict__ x0, const float* __restrict__ x1,
    const float* __restrict__ x2, const int* __restrict__ labp,
    float* __restrict__ out)
{
    extern __shared__ float sT[];             // 4 * CGPAD floats
    __shared__ int   slab[NN];
    __shared__ float pcmax[2][NCLS][32];

    const int bid = blockIdx.x;               // [0, 336)
    int level, b, tile;
    if (bid < 256)      { level = 0; b = bid >> 7;              tile = bid & 127; }
    else if (bid < 320) { level = 1; int q = bid - 256; b = q >> 5; tile = q & 31; }
    else                { level = 2; int q = bid - 320; b = q >> 3; tile = q & 7;  }

    const int W  = 64 >> level;
    const int HW = W * W;
    const float* feat = (level == 0) ? x0 : (level == 1) ? x1 : x2;
    const size_t outOff = (level == 0) ? 0
                        : (level == 1) ? (size_t)(BB * 266 * 4096)
                        : (size_t)(BB * 266 * (4096 + 1024));

    // stage templates (16B pad between cgroups) + labels
    {
        const float4* src = (const float4*)(g_tmpl + (size_t)(level * BB + b) * CC * NN);
        float4* dst = (float4*)sT;
        for (int i = threadIdx.x; i < CC * NN / 4; i += 256) {
            int cg = i >> 10;                 // 1024 float4 per cgroup
            dst[cg * (CGPAD / 4) + (i & 1023)] = src[i];
        }
        if (threadIdx.x < NN) {
            int lstr = lab_stride(labp);
            slab[threadIdx.x] = labp[(b * NN + threadIdx.x) * lstr];
        }
    }
    __syncthreads();

    const int lane = threadIdx.x & 31;
    const int warp = threadIdx.x >> 5;
    const int px8  = lane & 7;
    const int cg   = lane >> 3;               // channel group 0..3
    const int up   = warp & 1;                // user half 0..1
    const int pb   = warp >> 1;               // pixel sub-block 0..3
    const int p    = tile * 32 + pb * 8 + px8;

    const float* fp = feat + ((size_t)(b * CC + cg * 64)) * HW + p;
    float*       op = out + outOff + ((size_t)(b * 266 + cg * 64)) * HW + p;

    uint32_t sbase;
    asm("{ .reg .u64 t; cvta.to.shared.u64 t, %1; cvt.u32.u64 %0, t; }"
        : "=r"(sbase) : "l"(sT));
    sbase += (uint32_t)(cg * CGPAD + up * 32) * 4u;

    unsigned long long acc[16];               // acc[j] holds users (2j, 2j+1)
    #pragma unroll
    for (int i = 0; i < 16; i++) acc[i] = 0ULL;

    #pragma unroll 4
    for (int c = 0; c < 64; c++) {
        const float f = __ldg(fp + (size_t)c * HW);
        if (up == 0) op[(size_t)c * HW] = f;  // feat passthrough (warp-uniform)
        unsigned long long f2;
        {
            uint32_t fb_ = __float_as_uint(f);
            asm("mov.b64 %0, {%1, %1};" : "=l"(f2) : "r"(fb_));
        }
        const uint32_t a = sbase + (uint32_t)c * 256u;
        #pragma unroll
        for (int q = 0; q < 8; q++) {
            unsigned long long t0, t1;
            asm volatile("ld.shared.v2.b64 {%0, %1}, [%2];"
                         : "=l"(t0), "=l"(t1) : "r"(a + q * 16));
            asm("fma.rn.f32x2 %0, %1, %2, %0;" : "+l"(acc[2 * q])     : "l"(t0), "l"(f2));
            asm("fma.rn.f32x2 %0, %1, %2, %0;" : "+l"(acc[2 * q + 1]) : "l"(t1), "l"(f2));
        }
    }

    // sum the 4 channel groups (packed adds over lane bits 3,4)
    #pragma unroll
    for (int i = 0; i < 16; i++) {
        unsigned long long o = __shfl_xor_sync(0xffffffffu, acc[i], 8);
        asm("add.rn.f32x2 %0, %0, %1;" : "+l"(acc[i]) : "l"(o));
        o = __shfl_xor_sync(0xffffffffu, acc[i], 16);
        asm("add.rn.f32x2 %0, %0, %1;" : "+l"(acc[i]) : "l"(o));
    }

    // lanes cg==0 hold full sums for this warp's 32 users
    if (cg == 0) {
        #pragma unroll
        for (int k = 0; k < NCLS; k++) {
            float m = -FLT_MAX;
            #pragma unroll
            for (int u = 0; u < 32; u++) {
                float v = (u & 1) ? __uint_as_float((uint32_t)(acc[u >> 1] >> 32))
                                  : __uint_as_float((uint32_t)(acc[u >> 1] & 0xffffffffu));
                if (slab[up * 32 + u] == k + 1) m = fmaxf(m, v);
            }
            pcmax[up][k][pb * 8 + px8] = m;
        }
    }
    __syncthreads();

    // combine user halves, apply any_cls -> 0, write class channels.
    // NCLS*32 = 320 > blockDim (256): MUST loop (R2/R3 bug: classes 8,9 unwritten)
    for (int t = threadIdx.x; t < NCLS * 32; t += 256) {
        const int k   = t >> 5;
        const int pix = t & 31;
        float v = fmaxf(pcmax[0][k][pix], pcmax[1][k][pix]);
        if (v == -FLT_MAX) v = 0.f;
        out[outOff + ((size_t)(b * 266 + 256 + k)) * HW + tile * 32 + pix] = v;
    }
}

// ---------------------------------------------------------------------------
extern "C" void kernel_launch(void* const* d_in, const int* in_sizes, int n_in,
                              void* d_out, int out_size)
{
    const float* x0      = (const float*)d_in[0];
    const float* x1      = (const float*)d_in[1];
    const float* x2      = (const float*)d_in[2];
    const float* centers = (const float*)d_in[3];
    const int*   idxp    = (const int*)d_in[4];
    const int*   labp    = (const int*)d_in[5];
    float* out = (float*)d_out;

    const int smem = 4 * CGPAD * (int)sizeof(float);
    cudaFuncSetAttribute(cor_kernel, cudaFuncAttributeMaxDynamicSharedMemorySize, smem);

    tmpl_kernel<<<3 * BB * NN, CC>>>(x0, x1, x2, centers, idxp, labp);
    cor_kernel<<<336, 256, smem>>>(x0, x1, x2, labp, out);
}